// round 9
// baseline (speedup 1.0000x reference)
#include <cuda_runtime.h>
#include <cuda_bf16.h>
#include <cuda_fp16.h>
#include <cstdint>

#define MAXN 100000
#define MAXE 1600000

// ---------------- device scratch ----------------
__device__ int      g_is64;
__device__ int      g_deg[MAXN];
__device__ int      g_off[MAXN + 1];
__device__ int      g_cur[MAXN];
__device__ int      g_bsum[128];
__device__ int      g_bucket[MAXE];
__device__ __half   g_x16[(size_t)MAXN * 128];   // fp16 copy of x
__device__ __half   g_agg16[(size_t)MAXN * 128]; // layer1 agg (fp16)
__device__ __half   g_p16[(size_t)MAXN * 256];   // partial: x@W1r + b1 (fp16)
__device__ __half   g_h16[(size_t)MAXN * 256];   // hidden activations (fp16)
__device__ __half   g_t16[(size_t)MAXN * 64];    // layer2 t = h@W2l (fp16, aggregated)
__device__ float    g_u[(size_t)MAXN * 64];      // layer2 u = h@W2r (fp32)

// ---------------- edge dtype detection ----------------
__global__ void detect_kernel(const int* __restrict__ w) {
    __shared__ int any;
    if (threadIdx.x == 0) any = 0;
    __syncthreads();
    if (w[2 * threadIdx.x + 1] != 0) atomicOr(&any, 1);
    __syncthreads();
    if (threadIdx.x == 0) g_is64 = (any == 0) ? 1 : 0;
}

__device__ __forceinline__ int load_idx(const void* ei, int pos) {
    if (g_is64) return (int)((const long long*)ei)[pos];
    return ((const int*)ei)[pos];
}

// ---------------- x -> fp16 copy, fused with g_deg zeroing ----------------
__global__ void convert_x_kernel(const float* __restrict__ x, int N) {
    int i = blockIdx.x * blockDim.x + threadIdx.x;
    int total4 = N * 32;
    if (i < total4) {
        float4 v = ((const float4*)x)[i];
        __half2 a = __floats2half2_rn(v.x, v.y);
        __half2 b = __floats2half2_rn(v.z, v.w);
        uint2 o;
        o.x = *reinterpret_cast<unsigned*>(&a);
        o.y = *reinterpret_cast<unsigned*>(&b);
        *(uint2*)&g_x16[(size_t)i * 4] = o;
    }
    if (i < N) g_deg[i] = 0;
}

// ---------------- CSR construction ----------------
__global__ void count_kernel(const void* __restrict__ ei, int E, int N) {
    int e = blockIdx.x * blockDim.x + threadIdx.x;
    if (e < E) {
        int d = load_idx(ei, E + e);
        if ((unsigned)d < (unsigned)N) atomicAdd(&g_deg[d], 1);
    }
}

__global__ void scan_blocks(int N) {
    __shared__ int wsum[32];
    int i = blockIdx.x * 1024 + threadIdx.x;
    int lane = threadIdx.x & 31, wid = threadIdx.x >> 5;
    int v = (i < N) ? g_deg[i] : 0;
    int s = v;
    #pragma unroll
    for (int o = 1; o < 32; o <<= 1) {
        int t = __shfl_up_sync(0xffffffffu, s, o);
        if (lane >= o) s += t;
    }
    if (lane == 31) wsum[wid] = s;
    __syncthreads();
    if (wid == 0) {
        int ws = wsum[lane];
        #pragma unroll
        for (int o = 1; o < 32; o <<= 1) {
            int t = __shfl_up_sync(0xffffffffu, ws, o);
            if (lane >= o) ws += t;
        }
        wsum[lane] = ws;
    }
    __syncthreads();
    int incl = s + (wid > 0 ? wsum[wid - 1] : 0);
    if (i < N) g_off[i] = incl - v;
    if (threadIdx.x == 1023) g_bsum[blockIdx.x] = incl;
}

__global__ void scan_bsums(int B) {
    int lane = threadIdx.x;
    int carry = 0;
    for (int base = 0; base < B; base += 32) {
        int i = base + lane;
        int v = (i < B) ? g_bsum[i] : 0;
        int s = v;
        #pragma unroll
        for (int o = 1; o < 32; o <<= 1) {
            int t = __shfl_up_sync(0xffffffffu, s, o);
            if (lane >= o) s += t;
        }
        if (i < B) g_bsum[i] = carry + s - v;
        carry += __shfl_sync(0xffffffffu, s, 31);
    }
}

__global__ void finalize_off(int N, int E) {
    int i = blockIdx.x * blockDim.x + threadIdx.x;
    if (i < N) {
        int o = g_off[i] + g_bsum[i >> 10];
        g_off[i] = o;
        g_cur[i] = o;
    }
    if (i == 0) g_off[N] = E;
}

__global__ void fill_kernel(const void* __restrict__ ei, int E, int N) {
    int e = blockIdx.x * blockDim.x + threadIdx.x;
    if (e < E) {
        int s = load_idx(ei, e);
        int d = load_idx(ei, E + e);
        if ((unsigned)d < (unsigned)N && (unsigned)s < (unsigned)N) {
            int pos = atomicAdd(&g_cur[d], 1);
            g_bucket[pos] = s;
        }
    }
}

__device__ __forceinline__ void acc_h4(float4& acc, uint2 w) {
    __half2 h0 = *reinterpret_cast<__half2*>(&w.x);
    __half2 h1 = *reinterpret_cast<__half2*>(&w.y);
    float2 f0 = __half22float2(h0);
    float2 f1 = __half22float2(h1);
    acc.x += f0.x; acc.y += f0.y; acc.z += f1.x; acc.w += f1.y;
}

__device__ __forceinline__ unsigned packh2(float a, float b) {
    __half2 h = __floats2half2_rn(a, b);
    return *reinterpret_cast<unsigned*>(&h);
}

// ---------------- layer-1 mean aggregation (C=128, fp16 in/out), warp per node ----------------
__global__ void agg128_kernel(int N) {
    int lane = threadIdx.x & 31;
    int node = blockIdx.x * 4 + (threadIdx.x >> 5);
    if (node >= N) return;
    int beg = g_off[node], end = g_off[node + 1];
    float4 acc = make_float4(0.f, 0.f, 0.f, 0.f);
    int e = beg;
    for (; e + 4 <= end; e += 4) {
        int s0 = g_bucket[e], s1 = g_bucket[e + 1], s2 = g_bucket[e + 2], s3 = g_bucket[e + 3];
        uint2 w0 = *(const uint2*)&g_x16[(size_t)s0 * 128 + lane * 4];
        uint2 w1 = *(const uint2*)&g_x16[(size_t)s1 * 128 + lane * 4];
        uint2 w2 = *(const uint2*)&g_x16[(size_t)s2 * 128 + lane * 4];
        uint2 w3 = *(const uint2*)&g_x16[(size_t)s3 * 128 + lane * 4];
        acc_h4(acc, w0); acc_h4(acc, w1); acc_h4(acc, w2); acc_h4(acc, w3);
    }
    for (; e < end; ++e) {
        int s = g_bucket[e];
        uint2 w = *(const uint2*)&g_x16[(size_t)s * 128 + lane * 4];
        acc_h4(acc, w);
    }
    float inv = (end > beg) ? 1.f / (float)(end - beg) : 0.f;
    uint2 o;
    o.x = packh2(acc.x * inv, acc.y * inv);
    o.y = packh2(acc.z * inv, acc.w * inv);
    *(uint2*)&g_agg16[(size_t)node * 128 + lane * 4] = o;
}

// ---------------- fp16 MMA GEMMs (m16n8k16) ----------------
// Block tile 128x128, BK=32, 256 threads = 8 warps (2m x 4n), warp tile 64x32.
// MODE 0: p16 = x(fp32)@W1r + b1          K=128, NO=256 (grid.x=2), no act
// MODE 1: h16 = relu(agg16@W1l + p16)     K=128, NO=256 (grid.x=2)
// MODE 2: [t16|u] = h16 @ [W2l|W2r]       K=256, NO=128 (grid.x=1)

#define MMA_H16(d, a, b)                                                        \
    asm volatile(                                                               \
        "mma.sync.aligned.m16n8k16.row.col.f32.f16.f16.f32 "                    \
        "{%0,%1,%2,%3}, {%4,%5,%6,%7}, {%8,%9}, {%0,%1,%2,%3};"                 \
        : "+f"(d[0]), "+f"(d[1]), "+f"(d[2]), "+f"(d[3])                        \
        : "r"(a[0]), "r"(a[1]), "r"(a[2]), "r"(a[3]), "r"(b[0]), "r"(b[1]))

template <int MODE>
__global__ void __launch_bounds__(256, 2)
gemm_h16(const float* __restrict__ X,
         const float* __restrict__ Wa, const float* __restrict__ Wb,
         const float* __restrict__ bias, int M) {
    __shared__ unsigned As[128][20];
    __shared__ unsigned Ws[16][136];

    const int KTOT = (MODE == 2) ? 256 : 128;

    int tid = threadIdx.x;
    int lane = tid & 31;
    int wid = tid >> 5;
    int warp_m = wid & 1;
    int warp_n = wid >> 1;
    int qk = lane & 3;
    int qr = lane >> 2;
    int row0 = blockIdx.y * 128;
    int col0 = blockIdx.x * 128;

    float d[4][4][4];
    #pragma unroll
    for (int i = 0; i < 4; i++)
        #pragma unroll
        for (int j = 0; j < 4; j++)
            #pragma unroll
            for (int q = 0; q < 4; q++) d[i][j][q] = 0.f;

    for (int k0 = 0; k0 < KTOT; k0 += 32) {
        // ---- A tile: 128 rows x 32 halves ----
        #pragma unroll
        for (int it = 0; it < 2; it++) {
            int f = tid + it * 256;      // 0..511
            int m = f >> 2;              // row 0..127
            int q = f & 3;               // 8-half group
            int grow = row0 + m;
            if (MODE == 0) {
                uint4 o = make_uint4(0, 0, 0, 0);
                if (grow < M) {
                    const float* xp = &X[(size_t)grow * 128 + k0 + q * 8];
                    float4 v0 = *(const float4*)xp;
                    float4 v1 = *(const float4*)(xp + 4);
                    o.x = packh2(v0.x, v0.y); o.y = packh2(v0.z, v0.w);
                    o.z = packh2(v1.x, v1.y); o.w = packh2(v1.z, v1.w);
                }
                *(uint4*)&As[m][q * 4] = o;
            } else {
                uint4 v = make_uint4(0, 0, 0, 0);
                if (grow < M) {
                    if (MODE == 1)
                        v = *(const uint4*)&g_agg16[(size_t)grow * 128 + k0 + q * 8];
                    else
                        v = *(const uint4*)&g_h16[(size_t)grow * 256 + k0 + q * 8];
                }
                *(uint4*)&As[m][q * 4] = v;
            }
        }
        // ---- W tile: 32 k x 128 n, packed as k-pairs ----
        #pragma unroll
        for (int it = 0; it < 2; it++) {
            int task = tid + it * 256;
            int k2 = task >> 5;          // 0..15
            int n = (task & 31) * 4;     // 0..124
            float4 w0, w1;
            if (MODE != 2) {
                int kr = k0 + 2 * k2;
                w0 = *(const float4*)&Wa[(size_t)kr * 256 + col0 + n];
                w1 = *(const float4*)&Wa[(size_t)(kr + 1) * 256 + col0 + n];
            } else {
                int kg = k0 + 2 * k2;
                if (n < 64) {
                    w0 = *(const float4*)&Wa[(size_t)kg * 64 + n];
                    w1 = *(const float4*)&Wa[(size_t)(kg + 1) * 64 + n];
                } else {
                    w0 = *(const float4*)&Wb[(size_t)kg * 64 + (n - 64)];
                    w1 = *(const float4*)&Wb[(size_t)(kg + 1) * 64 + (n - 64)];
                }
            }
            uint4 o;
            o.x = packh2(w0.x, w1.x);
            o.y = packh2(w0.y, w1.y);
            o.z = packh2(w0.z, w1.z);
            o.w = packh2(w0.w, w1.w);
            *(uint4*)&Ws[k2][n] = o;
        }
        __syncthreads();

        #pragma unroll
        for (int kk = 0; kk < 2; kk++) {
            int k2b = kk * 8;
            unsigned a[4][4], b[4][2];
            #pragma unroll
            for (int mf = 0; mf < 4; mf++) {
                int mrow = warp_m * 64 + mf * 16 + qr;
                a[mf][0] = As[mrow][k2b + qk];
                a[mf][1] = As[mrow + 8][k2b + qk];
                a[mf][2] = As[mrow][k2b + qk + 4];
                a[mf][3] = As[mrow + 8][k2b + qk + 4];
            }
            #pragma unroll
            for (int nf = 0; nf < 4; nf++) {
                int ncol = warp_n * 32 + nf * 8 + qr;
                b[nf][0] = Ws[k2b + qk][ncol];
                b[nf][1] = Ws[k2b + qk + 4][ncol];
            }
            #pragma unroll
            for (int mf = 0; mf < 4; mf++)
                #pragma unroll
                for (int nf = 0; nf < 4; nf++)
                    MMA_H16(d[mf][nf], a[mf], b[nf]);
        }
        __syncthreads();
    }

    // ---- epilogue ----
    #pragma unroll
    for (int nf = 0; nf < 4; nf++) {
        int col = col0 + warp_n * 32 + nf * 8 + qk * 2;
        if (MODE == 0) {
            float2 bv = *(const float2*)&bias[col];
            #pragma unroll
            for (int mf = 0; mf < 4; mf++) {
                int r0 = row0 + warp_m * 64 + mf * 16 + qr;
                if (r0 < M) {
                    unsigned hh = packh2(d[mf][nf][0] + bv.x, d[mf][nf][1] + bv.y);
                    *(unsigned*)&g_p16[(size_t)r0 * 256 + col] = hh;
                }
                if (r0 + 8 < M) {
                    unsigned hh = packh2(d[mf][nf][2] + bv.x, d[mf][nf][3] + bv.y);
                    *(unsigned*)&g_p16[(size_t)(r0 + 8) * 256 + col] = hh;
                }
            }
        } else if (MODE == 1) {
            #pragma unroll
            for (int mf = 0; mf < 4; mf++) {
                int r0 = row0 + warp_m * 64 + mf * 16 + qr;
                if (r0 < M) {
                    unsigned pw = *(const unsigned*)&g_p16[(size_t)r0 * 256 + col];
                    float2 pf = __half22float2(*reinterpret_cast<__half2*>(&pw));
                    unsigned hh = packh2(fmaxf(d[mf][nf][0] + pf.x, 0.f),
                                         fmaxf(d[mf][nf][1] + pf.y, 0.f));
                    *(unsigned*)&g_h16[(size_t)r0 * 256 + col] = hh;
                }
                if (r0 + 8 < M) {
                    unsigned pw = *(const unsigned*)&g_p16[(size_t)(r0 + 8) * 256 + col];
                    float2 pf = __half22float2(*reinterpret_cast<__half2*>(&pw));
                    unsigned hh = packh2(fmaxf(d[mf][nf][2] + pf.x, 0.f),
                                         fmaxf(d[mf][nf][3] + pf.y, 0.f));
                    *(unsigned*)&g_h16[(size_t)(r0 + 8) * 256 + col] = hh;
                }
            }
        } else {
            #pragma unroll
            for (int mf = 0; mf < 4; mf++) {
                int r0 = row0 + warp_m * 64 + mf * 16 + qr;
                if (col < 64) {
                    if (r0 < M) {
                        unsigned hh = packh2(d[mf][nf][0], d[mf][nf][1]);
                        *(unsigned*)&g_t16[(size_t)r0 * 64 + col] = hh;
                    }
                    if (r0 + 8 < M) {
                        unsigned hh = packh2(d[mf][nf][2], d[mf][nf][3]);
                        *(unsigned*)&g_t16[(size_t)(r0 + 8) * 64 + col] = hh;
                    }
                } else {
                    if (r0 < M) {
                        float2 o = make_float2(d[mf][nf][0], d[mf][nf][1]);
                        *(float2*)&g_u[(size_t)r0 * 64 + (col - 64)] = o;
                    }
                    if (r0 + 8 < M) {
                        float2 o = make_float2(d[mf][nf][2], d[mf][nf][3]);
                        *(float2*)&g_u[(size_t)(r0 + 8) * 64 + (col - 64)] = o;
                    }
                }
            }
        }
    }
}

// ---------------- final: out = sigmoid( mean_agg(t16) + u + b2 ) ----------------
__global__ void agg_sig_kernel(const float* __restrict__ b2, float* __restrict__ out, int N) {
    int lane = threadIdx.x & 15;
    int node = blockIdx.x * 8 + (threadIdx.x >> 4);
    if (node >= N) return;
    int beg = g_off[node], end = g_off[node + 1];
    float4 acc = make_float4(0.f, 0.f, 0.f, 0.f);
    int e = beg;
    for (; e + 4 <= end; e += 4) {
        int s0 = g_bucket[e], s1 = g_bucket[e + 1], s2 = g_bucket[e + 2], s3 = g_bucket[e + 3];
        uint2 w0 = *(const uint2*)&g_t16[(size_t)s0 * 64 + lane * 4];
        uint2 w1 = *(const uint2*)&g_t16[(size_t)s1 * 64 + lane * 4];
        uint2 w2 = *(const uint2*)&g_t16[(size_t)s2 * 64 + lane * 4];
        uint2 w3 = *(const uint2*)&g_t16[(size_t)s3 * 64 + lane * 4];
        acc_h4(acc, w0); acc_h4(acc, w1); acc_h4(acc, w2); acc_h4(acc, w3);
    }
    for (; e < end; ++e) {
        int s = g_bucket[e];
        uint2 w = *(const uint2*)&g_t16[(size_t)s * 64 + lane * 4];
        acc_h4(acc, w);
    }
    float inv = (end > beg) ? 1.f / (float)(end - beg) : 0.f;
    float4 u = *(const float4*)&g_u[(size_t)node * 64 + lane * 4];
    float4 bv = *(const float4*)&b2[lane * 4];
    float4 o;
    o.x = 1.f / (1.f + __expf(-(acc.x * inv + u.x + bv.x)));
    o.y = 1.f / (1.f + __expf(-(acc.y * inv + u.y + bv.y)));
    o.z = 1.f / (1.f + __expf(-(acc.z * inv + u.z + bv.z)));
    o.w = 1.f / (1.f + __expf(-(acc.w * inv + u.w + bv.w)));
    *(float4*)&out[(size_t)node * 64 + lane * 4] = o;
}

// ---------------- launch ----------------
extern "C" void kernel_launch(void* const* d_in, const int* in_sizes, int n_in,
                              void* d_out, int out_size) {
    const float* x   = (const float*)d_in[0];
    const void*  ei  = d_in[1];
    const float* W1l = (const float*)d_in[2];
    const float* W1r = (const float*)d_in[3];
    const float* b1  = (const float*)d_in[4];
    const float* W2l = (const float*)d_in[5];
    const float* W2r = (const float*)d_in[6];
    const float* b2  = (const float*)d_in[7];
    float* out = (float*)d_out;

    int N = in_sizes[0] / 128;
    int E = in_sizes[1] / 2;
    int B = (N + 1023) / 1024;

    // One-time side stream + events (created on the non-captured correctness call)
    static cudaStream_t s2 = nullptr;
    static cudaEvent_t evFork = nullptr, evJoin = nullptr;
    if (s2 == nullptr) {
        cudaStreamCreateWithFlags(&s2, cudaStreamNonBlocking);
        cudaEventCreateWithFlags(&evFork, cudaEventDisableTiming);
        cudaEventCreateWithFlags(&evJoin, cudaEventDisableTiming);
    }

    // ---- fork: gemm0a (p16 = x@W1r + b1) on side stream, independent of CSR ----
    cudaEventRecord(evFork, 0);
    cudaStreamWaitEvent(s2, evFork, 0);
    {
        dim3 grid(2, (N + 127) / 128);
        gemm_h16<0><<<grid, 256, 0, s2>>>(x, W1r, nullptr, b1, N);
    }
    cudaEventRecord(evJoin, s2);

    // ---- main stream: CSR build + layer-1 aggregation ----
    detect_kernel<<<1, 64>>>((const int*)ei);
    convert_x_kernel<<<(N * 32 + 255) / 256, 256>>>(x, N);   // also zeroes g_deg
    count_kernel<<<(E + 255) / 256, 256>>>(ei, E, N);
    scan_blocks<<<B, 1024>>>(N);
    scan_bsums<<<1, 32>>>(B);
    finalize_off<<<(N + 255) / 256, 256>>>(N, E);
    fill_kernel<<<(E + 255) / 256, 256>>>(ei, E, N);
    agg128_kernel<<<(N + 3) / 4, 128>>>(N);

    // ---- join, then the dependent tail ----
    cudaStreamWaitEvent(0, evJoin, 0);
    {
        dim3 grid(2, (N + 127) / 128);
        gemm_h16<1><<<grid, 256>>>(nullptr, W1l, nullptr, nullptr, N);
    }
    {
        dim3 grid(1, (N + 127) / 128);
        gemm_h16<2><<<grid, 256>>>(nullptr, W2l, W2r, nullptr, N);
    }
    agg_sig_kernel<<<(N + 7) / 8, 128>>>(b2, out, N);
}

// round 10
// speedup vs baseline: 1.3053x; 1.3053x over previous
#include <cuda_runtime.h>
#include <cuda_bf16.h>
#include <cuda_fp16.h>
#include <cstdint>

#define MAXN 100000
#define MAXE 1600000

// ---------------- device scratch ----------------
__device__ int      g_is64;
__device__ int      g_deg[MAXN];
__device__ int      g_off[MAXN + 1];
__device__ int      g_cur[MAXN];
__device__ int      g_bsum[128];
__device__ int      g_bucket[MAXE];
__device__ __half   g_x16[(size_t)MAXN * 128];   // fp16 copy of x
__device__ __half   g_agg16[(size_t)MAXN * 128]; // layer1 agg (fp16)
__device__ __half   g_h16[(size_t)MAXN * 256];   // hidden activations (fp16)
__device__ __half   g_t16[(size_t)MAXN * 64];    // layer2 t = h@W2l (fp16, aggregated)
__device__ float    g_u[(size_t)MAXN * 64];      // layer2 u = h@W2r (fp32)
// pre-packed fp16 weights: word [k2][n] = {W[2k2][n], W[2k2+1][n]}
__device__ unsigned g_w1p[128 * 256];            // W1 = [W1l;W1r] row-concat, K=256, N=256
__device__ unsigned g_w2p[128 * 128];            // W2 = [W2l|W2r] col-concat, K=256, N=128

// ---------------- edge dtype detection ----------------
__global__ void detect_kernel(const int* __restrict__ w) {
    __shared__ int any;
    if (threadIdx.x == 0) any = 0;
    __syncthreads();
    if (w[2 * threadIdx.x + 1] != 0) atomicOr(&any, 1);
    __syncthreads();
    if (threadIdx.x == 0) g_is64 = (any == 0) ? 1 : 0;
}

__device__ __forceinline__ int load_idx(const void* ei, int pos) {
    if (g_is64) return (int)((const long long*)ei)[pos];
    return ((const int*)ei)[pos];
}

__device__ __forceinline__ unsigned packh2(float a, float b) {
    __half2 h = __floats2half2_rn(a, b);
    return *reinterpret_cast<unsigned*>(&h);
}

// ---------------- prep: x->fp16, zero deg, pre-pack weights ----------------
__global__ void prep_kernel(const float* __restrict__ x,
                            const float* __restrict__ W1l, const float* __restrict__ W1r,
                            const float* __restrict__ W2l, const float* __restrict__ W2r,
                            int N, int convBlocks) {
    if ((int)blockIdx.x < convBlocks) {
        int i = blockIdx.x * 256 + threadIdx.x;
        int total4 = N * 32;
        if (i < total4) {
            float4 v = ((const float4*)x)[i];
            uint2 o;
            o.x = packh2(v.x, v.y);
            o.y = packh2(v.z, v.w);
            *(uint2*)&g_x16[(size_t)i * 4] = o;
        }
        if (i < N) g_deg[i] = 0;
    } else {
        int w = (blockIdx.x - convBlocks) * 256 + threadIdx.x;
        if (w < 128 * 256) {
            // g_w1p: k2 = w>>8 (0..127), n = w&255. rows 2k2,2k2+1 of [W1l;W1r]
            int k2 = w >> 8, n = w & 255;
            int r0 = 2 * k2;
            float a, b;
            if (r0 < 128) {
                a = W1l[(size_t)r0 * 256 + n];
                b = W1l[(size_t)(r0 + 1) * 256 + n];
            } else {
                a = W1r[(size_t)(r0 - 128) * 256 + n];
                b = W1r[(size_t)(r0 - 127) * 256 + n];
            }
            g_w1p[w] = packh2(a, b);
        } else {
            int w2 = w - 128 * 256;
            if (w2 < 128 * 128) {
                // g_w2p: k2 = w2>>7, n = w2&127. rows 2k2,2k2+1, col-concat [W2l|W2r]
                int k2 = w2 >> 7, n = w2 & 127;
                int r0 = 2 * k2;
                float a, b;
                if (n < 64) {
                    a = W2l[(size_t)r0 * 64 + n];
                    b = W2l[(size_t)(r0 + 1) * 64 + n];
                } else {
                    a = W2r[(size_t)r0 * 64 + (n - 64)];
                    b = W2r[(size_t)(r0 + 1) * 64 + (n - 64)];
                }
                g_w2p[w2] = packh2(a, b);
            }
        }
    }
}

// ---------------- CSR construction ----------------
__global__ void count_kernel(const void* __restrict__ ei, int E, int N) {
    int e = blockIdx.x * blockDim.x + threadIdx.x;
    if (e < E) {
        int d = load_idx(ei, E + e);
        if ((unsigned)d < (unsigned)N) atomicAdd(&g_deg[d], 1);
    }
}

__global__ void scan_blocks(int N) {
    __shared__ int wsum[32];
    int i = blockIdx.x * 1024 + threadIdx.x;
    int lane = threadIdx.x & 31, wid = threadIdx.x >> 5;
    int v = (i < N) ? g_deg[i] : 0;
    int s = v;
    #pragma unroll
    for (int o = 1; o < 32; o <<= 1) {
        int t = __shfl_up_sync(0xffffffffu, s, o);
        if (lane >= o) s += t;
    }
    if (lane == 31) wsum[wid] = s;
    __syncthreads();
    if (wid == 0) {
        int ws = wsum[lane];
        #pragma unroll
        for (int o = 1; o < 32; o <<= 1) {
            int t = __shfl_up_sync(0xffffffffu, ws, o);
            if (lane >= o) ws += t;
        }
        wsum[lane] = ws;
    }
    __syncthreads();
    int incl = s + (wid > 0 ? wsum[wid - 1] : 0);
    if (i < N) g_off[i] = incl - v;
    if (threadIdx.x == 1023) g_bsum[blockIdx.x] = incl;
}

__global__ void scan_bsums(int B) {
    int lane = threadIdx.x;
    int carry = 0;
    for (int base = 0; base < B; base += 32) {
        int i = base + lane;
        int v = (i < B) ? g_bsum[i] : 0;
        int s = v;
        #pragma unroll
        for (int o = 1; o < 32; o <<= 1) {
            int t = __shfl_up_sync(0xffffffffu, s, o);
            if (lane >= o) s += t;
        }
        if (i < B) g_bsum[i] = carry + s - v;
        carry += __shfl_sync(0xffffffffu, s, 31);
    }
}

__global__ void finalize_off(int N, int E) {
    int i = blockIdx.x * blockDim.x + threadIdx.x;
    if (i < N) {
        int o = g_off[i] + g_bsum[i >> 10];
        g_off[i] = o;
        g_cur[i] = o;
    }
    if (i == 0) g_off[N] = E;
}

__global__ void fill_kernel(const void* __restrict__ ei, int E, int N) {
    int e = blockIdx.x * blockDim.x + threadIdx.x;
    if (e < E) {
        int s = load_idx(ei, e);
        int d = load_idx(ei, E + e);
        if ((unsigned)d < (unsigned)N && (unsigned)s < (unsigned)N) {
            int pos = atomicAdd(&g_cur[d], 1);
            g_bucket[pos] = s;
        }
    }
}

__device__ __forceinline__ void acc_h4(float4& acc, uint2 w) {
    __half2 h0 = *reinterpret_cast<__half2*>(&w.x);
    __half2 h1 = *reinterpret_cast<__half2*>(&w.y);
    float2 f0 = __half22float2(h0);
    float2 f1 = __half22float2(h1);
    acc.x += f0.x; acc.y += f0.y; acc.z += f1.x; acc.w += f1.y;
}

// ---------------- layer-1 mean aggregation (C=128, fp16 in/out), warp per node ----------------
__global__ void agg128_kernel(int N) {
    int lane = threadIdx.x & 31;
    int node = blockIdx.x * 4 + (threadIdx.x >> 5);
    if (node >= N) return;
    int beg = g_off[node], end = g_off[node + 1];
    float4 acc = make_float4(0.f, 0.f, 0.f, 0.f);
    int e = beg;
    for (; e + 4 <= end; e += 4) {
        int s0 = g_bucket[e], s1 = g_bucket[e + 1], s2 = g_bucket[e + 2], s3 = g_bucket[e + 3];
        uint2 w0 = *(const uint2*)&g_x16[(size_t)s0 * 128 + lane * 4];
        uint2 w1 = *(const uint2*)&g_x16[(size_t)s1 * 128 + lane * 4];
        uint2 w2 = *(const uint2*)&g_x16[(size_t)s2 * 128 + lane * 4];
        uint2 w3 = *(const uint2*)&g_x16[(size_t)s3 * 128 + lane * 4];
        acc_h4(acc, w0); acc_h4(acc, w1); acc_h4(acc, w2); acc_h4(acc, w3);
    }
    for (; e < end; ++e) {
        int s = g_bucket[e];
        uint2 w = *(const uint2*)&g_x16[(size_t)s * 128 + lane * 4];
        acc_h4(acc, w);
    }
    float inv = (end > beg) ? 1.f / (float)(end - beg) : 0.f;
    uint2 o;
    o.x = packh2(acc.x * inv, acc.y * inv);
    o.y = packh2(acc.z * inv, acc.w * inv);
    *(uint2*)&g_agg16[(size_t)node * 128 + lane * 4] = o;
}

// ---------------- fp16 MMA GEMMs (m16n8k16), register-staged prefetch ----------------
// Block tile 128x128, BK=32 halves (16 k2 words), 8 iters, 256 threads = 8 warps.
// MODE 0: h16 = relu([agg16|x16](K=256) @ g_w1p + b1), NO=256 (grid.x=2)
// MODE 1: [t16|u] = h16 (K=256) @ g_w2p,               NO=128 (grid.x=1)

#define MMA_H16(d, a, b)                                                        \
    asm volatile(                                                               \
        "mma.sync.aligned.m16n8k16.row.col.f32.f16.f16.f32 "                    \
        "{%0,%1,%2,%3}, {%4,%5,%6,%7}, {%8,%9}, {%0,%1,%2,%3};"                 \
        : "+f"(d[0]), "+f"(d[1]), "+f"(d[2]), "+f"(d[3])                        \
        : "r"(a[0]), "r"(a[1]), "r"(a[2]), "r"(a[3]), "r"(b[0]), "r"(b[1]))

template <int MODE>
__global__ void __launch_bounds__(256, 2)
gemm_h16(const float* __restrict__ bias, int M) {
    __shared__ unsigned As[128][20];
    __shared__ unsigned Ws[16][136];

    const int NI = 8;                       // K=256 / 32
    const int WSTRIDE = (MODE == 0) ? 256 : 128;
    const unsigned* __restrict__ Wp = (MODE == 0) ? g_w1p : g_w2p;

    int tid = threadIdx.x;
    int lane = tid & 31;
    int wid = tid >> 5;
    int warp_m = wid & 1;
    int warp_n = wid >> 1;
    int qk = lane & 3;
    int qr = lane >> 2;
    int row0 = blockIdx.y * 128;
    int col0 = blockIdx.x * 128;

    // per-thread tile-load coordinates
    int am = tid >> 2;          // A row for first uint4 (second: +64)
    int aq = tid & 3;           // 8-half group within 32
    int wk = tid >> 5;          // k2 row 0..7 for first uint4 (second: +8)
    int wn = (tid & 31) * 4;    // n word 0..124

    float d[4][4][4];
    #pragma unroll
    for (int i = 0; i < 4; i++)
        #pragma unroll
        for (int j = 0; j < 4; j++)
            #pragma unroll
            for (int q = 0; q < 4; q++) d[i][j][q] = 0.f;

    uint4 aR[2], wR[2];

    // ---- load tile `it` into registers ----
    auto load_tiles = [&](int it) {
        int k0 = it * 32;
        // A
        #pragma unroll
        for (int j = 0; j < 2; j++) {
            int grow = row0 + am + j * 64;
            uint4 v = make_uint4(0, 0, 0, 0);
            if (grow < M) {
                if (MODE == 0) {
                    const __half* src = (k0 < 128) ? g_agg16 : g_x16;
                    v = *(const uint4*)&src[(size_t)grow * 128 + (k0 & 127) + aq * 8];
                } else {
                    v = *(const uint4*)&g_h16[(size_t)grow * 256 + k0 + aq * 8];
                }
            }
            aR[j] = v;
        }
        // W (pre-packed): rows k2base..k2base+15
        int k2base = it * 16;
        #pragma unroll
        for (int j = 0; j < 2; j++) {
            int k2 = k2base + wk + j * 8;
            wR[j] = *(const uint4*)&Wp[(size_t)k2 * WSTRIDE + col0 + wn];
        }
    };

    auto store_tiles = [&]() {
        *(uint4*)&As[am][aq * 4] = aR[0];
        *(uint4*)&As[am + 64][aq * 4] = aR[1];
        *(uint4*)&Ws[wk][wn] = wR[0];
        *(uint4*)&Ws[wk + 8][wn] = wR[1];
    };

    load_tiles(0);
    for (int it = 0; it < NI; ++it) {
        store_tiles();
        __syncthreads();
        if (it + 1 < NI) load_tiles(it + 1);

        #pragma unroll
        for (int kk = 0; kk < 2; kk++) {
            int k2b = kk * 8;
            unsigned a[4][4], b[4][2];
            #pragma unroll
            for (int mf = 0; mf < 4; mf++) {
                int mrow = warp_m * 64 + mf * 16 + qr;
                a[mf][0] = As[mrow][k2b + qk];
                a[mf][1] = As[mrow + 8][k2b + qk];
                a[mf][2] = As[mrow][k2b + qk + 4];
                a[mf][3] = As[mrow + 8][k2b + qk + 4];
            }
            #pragma unroll
            for (int nf = 0; nf < 4; nf++) {
                int ncol = warp_n * 32 + nf * 8 + qr;
                b[nf][0] = Ws[k2b + qk][ncol];
                b[nf][1] = Ws[k2b + qk + 4][ncol];
            }
            #pragma unroll
            for (int mf = 0; mf < 4; mf++)
                #pragma unroll
                for (int nf = 0; nf < 4; nf++)
                    MMA_H16(d[mf][nf], a[mf], b[nf]);
        }
        __syncthreads();
    }

    // ---- epilogue ----
    #pragma unroll
    for (int nf = 0; nf < 4; nf++) {
        int col = col0 + warp_n * 32 + nf * 8 + qk * 2;
        if (MODE == 0) {
            float2 bv = *(const float2*)&bias[col];
            #pragma unroll
            for (int mf = 0; mf < 4; mf++) {
                int r0 = row0 + warp_m * 64 + mf * 16 + qr;
                if (r0 < M) {
                    unsigned hh = packh2(fmaxf(d[mf][nf][0] + bv.x, 0.f),
                                         fmaxf(d[mf][nf][1] + bv.y, 0.f));
                    *(unsigned*)&g_h16[(size_t)r0 * 256 + col] = hh;
                }
                if (r0 + 8 < M) {
                    unsigned hh = packh2(fmaxf(d[mf][nf][2] + bv.x, 0.f),
                                         fmaxf(d[mf][nf][3] + bv.y, 0.f));
                    *(unsigned*)&g_h16[(size_t)(r0 + 8) * 256 + col] = hh;
                }
            }
        } else {
            #pragma unroll
            for (int mf = 0; mf < 4; mf++) {
                int r0 = row0 + warp_m * 64 + mf * 16 + qr;
                if (col < 64) {
                    if (r0 < M) {
                        unsigned hh = packh2(d[mf][nf][0], d[mf][nf][1]);
                        *(unsigned*)&g_t16[(size_t)r0 * 64 + col] = hh;
                    }
                    if (r0 + 8 < M) {
                        unsigned hh = packh2(d[mf][nf][2], d[mf][nf][3]);
                        *(unsigned*)&g_t16[(size_t)(r0 + 8) * 64 + col] = hh;
                    }
                } else {
                    if (r0 < M) {
                        float2 o = make_float2(d[mf][nf][0], d[mf][nf][1]);
                        *(float2*)&g_u[(size_t)r0 * 64 + (col - 64)] = o;
                    }
                    if (r0 + 8 < M) {
                        float2 o = make_float2(d[mf][nf][2], d[mf][nf][3]);
                        *(float2*)&g_u[(size_t)(r0 + 8) * 64 + (col - 64)] = o;
                    }
                }
            }
        }
    }
}

// ---------------- final: out = sigmoid( mean_agg(t16) + u + b2 ) ----------------
__global__ void agg_sig_kernel(const float* __restrict__ b2, float* __restrict__ out, int N) {
    int lane = threadIdx.x & 15;
    int node = blockIdx.x * 8 + (threadIdx.x >> 4);
    if (node >= N) return;
    int beg = g_off[node], end = g_off[node + 1];
    float4 acc = make_float4(0.f, 0.f, 0.f, 0.f);
    int e = beg;
    for (; e + 4 <= end; e += 4) {
        int s0 = g_bucket[e], s1 = g_bucket[e + 1], s2 = g_bucket[e + 2], s3 = g_bucket[e + 3];
        uint2 w0 = *(const uint2*)&g_t16[(size_t)s0 * 64 + lane * 4];
        uint2 w1 = *(const uint2*)&g_t16[(size_t)s1 * 64 + lane * 4];
        uint2 w2 = *(const uint2*)&g_t16[(size_t)s2 * 64 + lane * 4];
        uint2 w3 = *(const uint2*)&g_t16[(size_t)s3 * 64 + lane * 4];
        acc_h4(acc, w0); acc_h4(acc, w1); acc_h4(acc, w2); acc_h4(acc, w3);
    }
    for (; e < end; ++e) {
        int s = g_bucket[e];
        uint2 w = *(const uint2*)&g_t16[(size_t)s * 64 + lane * 4];
        acc_h4(acc, w);
    }
    float inv = (end > beg) ? 1.f / (float)(end - beg) : 0.f;
    float4 u = *(const float4*)&g_u[(size_t)node * 64 + lane * 4];
    float4 bv = *(const float4*)&b2[lane * 4];
    float4 o;
    o.x = 1.f / (1.f + __expf(-(acc.x * inv + u.x + bv.x)));
    o.y = 1.f / (1.f + __expf(-(acc.y * inv + u.y + bv.y)));
    o.z = 1.f / (1.f + __expf(-(acc.z * inv + u.z + bv.z)));
    o.w = 1.f / (1.f + __expf(-(acc.w * inv + u.w + bv.w)));
    *(float4*)&out[(size_t)node * 64 + lane * 4] = o;
}

// ---------------- launch ----------------
extern "C" void kernel_launch(void* const* d_in, const int* in_sizes, int n_in,
                              void* d_out, int out_size) {
    const float* x   = (const float*)d_in[0];
    const void*  ei  = d_in[1];
    const float* W1l = (const float*)d_in[2];
    const float* W1r = (const float*)d_in[3];
    const float* b1  = (const float*)d_in[4];
    const float* W2l = (const float*)d_in[5];
    const float* W2r = (const float*)d_in[6];
    const float* b2  = (const float*)d_in[7];
    float* out = (float*)d_out;

    int N = in_sizes[0] / 128;
    int E = in_sizes[1] / 2;
    int B = (N + 1023) / 1024;

    int convBlocks = (N * 32 + 255) / 256;
    int packBlocks = (128 * 256 + 128 * 128 + 255) / 256;   // 192

    detect_kernel<<<1, 64>>>((const int*)ei);
    prep_kernel<<<convBlocks + packBlocks, 256>>>(x, W1l, W1r, W2l, W2r, N, convBlocks);
    count_kernel<<<(E + 255) / 256, 256>>>(ei, E, N);
    scan_blocks<<<B, 1024>>>(N);
    scan_bsums<<<1, 32>>>(B);
    finalize_off<<<(N + 255) / 256, 256>>>(N, E);
    fill_kernel<<<(E + 255) / 256, 256>>>(ei, E, N);

    agg128_kernel<<<(N + 3) / 4, 128>>>(N);
    {
        dim3 grid(2, (N + 127) / 128);
        gemm_h16<0><<<grid, 256>>>(b1, N);
    }
    {
        dim3 grid(1, (N + 127) / 128);
        gemm_h16<1><<<grid, 256>>>(nullptr, N);
    }
    agg_sig_kernel<<<(N + 7) / 8, 128>>>(b2, out, N);
}